// round 12
// baseline (speedup 1.0000x reference)
#include <cuda_runtime.h>
#include <cuda_bf16.h>
#include <cstdint>

#define N_NODES 20000
#define N_EDGES 160000
#define N_IN    512
#define N_OUT   512
#define M_PAD   20096            // 157 * 128

// Static device scratch (no runtime allocation; zero-initialized at load)
__device__ __nv_bfloat16  g_Ahi[(size_t)M_PAD * N_IN];   // 20.6 MB (padding rows stay 0)
__device__ __nv_bfloat16  g_Alo[(size_t)M_PAD * N_IN];   // 20.6 MB
__device__ __nv_bfloat16  g_Whi[(size_t)N_OUT * N_IN];
__device__ __nv_bfloat16  g_Wlo[(size_t)N_OUT * N_IN];
__device__ int            g_cnt[N_NODES];                // histogram, then fill cursor
__device__ int            g_ofs[N_NODES + 1];            // CSR row offsets
__device__ int            g_csr_col[N_EDGES];
__device__ float          g_csr_val[N_EDGES];

// ---------------------------------------------------------------------------
// Helpers
// ---------------------------------------------------------------------------
__device__ __forceinline__ uint32_t smem_u32(const void* p) {
    uint32_t a;
    asm("{ .reg .u64 t; cvta.to.shared.u64 t, %1; cvt.u32.u64 %0, t; }"
        : "=r"(a) : "l"(p));
    return a;
}

// Split 4 fp32 into bf16 hi (rn) and bf16 lo = bf16(a - float(hi)); packed pairs
__device__ __forceinline__ void split4(float4 f, uint32_t& hi0, uint32_t& hi1,
                                       uint32_t& lo0, uint32_t& lo1) {
    __nv_bfloat16 hx = __float2bfloat16(f.x);
    __nv_bfloat16 hy = __float2bfloat16(f.y);
    __nv_bfloat16 hz = __float2bfloat16(f.z);
    __nv_bfloat16 hw = __float2bfloat16(f.w);
    __nv_bfloat16 lx = __float2bfloat16(f.x - __bfloat162float(hx));
    __nv_bfloat16 ly = __float2bfloat16(f.y - __bfloat162float(hy));
    __nv_bfloat16 lz = __float2bfloat16(f.z - __bfloat162float(hz));
    __nv_bfloat16 lw = __float2bfloat16(f.w - __bfloat162float(hw));
    __nv_bfloat162 H0 = __halves2bfloat162(hx, hy);
    __nv_bfloat162 H1 = __halves2bfloat162(hz, hw);
    __nv_bfloat162 L0 = __halves2bfloat162(lx, ly);
    __nv_bfloat162 L1 = __halves2bfloat162(lz, lw);
    hi0 = *reinterpret_cast<uint32_t*>(&H0);
    hi1 = *reinterpret_cast<uint32_t*>(&H1);
    lo0 = *reinterpret_cast<uint32_t*>(&L0);
    lo1 = *reinterpret_cast<uint32_t*>(&L1);
}

__device__ __forceinline__ void cp_async16(uint32_t smem_addr, const void* gptr) {
    asm volatile("cp.async.cg.shared.global [%0], [%1], 16;"
                 :: "r"(smem_addr), "l"(gptr) : "memory");
}

__device__ __forceinline__ void ldsm_x4(uint32_t& r0, uint32_t& r1,
                                        uint32_t& r2, uint32_t& r3, uint32_t addr) {
    asm volatile("ldmatrix.sync.aligned.m8n8.x4.shared.b16 {%0,%1,%2,%3}, [%4];"
                 : "=r"(r0), "=r"(r1), "=r"(r2), "=r"(r3) : "r"(addr));
}

__device__ __forceinline__ void mma_bf16(float& c0, float& c1, float& c2, float& c3,
                                         uint32_t a0, uint32_t a1, uint32_t a2, uint32_t a3,
                                         uint32_t b0, uint32_t b1) {
    asm volatile(
        "mma.sync.aligned.m16n8k16.row.col.f32.bf16.bf16.f32 "
        "{%0,%1,%2,%3}, {%4,%5,%6,%7}, {%8,%9}, {%0,%1,%2,%3};"
        : "+f"(c0), "+f"(c1), "+f"(c2), "+f"(c3)
        : "r"(a0), "r"(a1), "r"(a2), "r"(a3), "r"(b0), "r"(b1));
}

__device__ __forceinline__ uint32_t sw128(uint32_t off) {
    return off ^ ((off >> 3) & 0x70);
}

// ---------------------------------------------------------------------------
// CSR build: zero counts -> histogram -> scan -> fill
// ---------------------------------------------------------------------------
__global__ void zero_cnt_kernel() {
    int i = blockIdx.x * blockDim.x + threadIdx.x;
    if (i < N_NODES) g_cnt[i] = 0;
}

__global__ void hist_kernel(const int* __restrict__ row, int E) {
    int e = blockIdx.x * blockDim.x + threadIdx.x;
    if (e < E) atomicAdd(&g_cnt[row[e]], 1);
}

// Single-block exclusive scan of g_cnt -> g_ofs; re-init g_cnt as fill cursor.
__global__ __launch_bounds__(1024) void scan_kernel() {
    __shared__ int s[1024];
    const int t = threadIdx.x;
    const int PER = 20;                        // 1024*20 = 20480 >= N_NODES
    const int beg = t * PER;
    const int end = min(beg + PER, N_NODES);

    int part = 0;
    for (int i = beg; i < end; i++) part += g_cnt[i];
    s[t] = part;
    __syncthreads();
    for (int off = 1; off < 1024; off <<= 1) {
        int v = (t >= off) ? s[t - off] : 0;
        __syncthreads();
        s[t] += v;
        __syncthreads();
    }
    int base = s[t] - part;                    // exclusive prefix
    for (int i = beg; i < end; i++) {
        int c = g_cnt[i];
        g_ofs[i] = base;
        g_cnt[i] = base;                       // cursor for fill
        base += c;
    }
    if (t == 1023) g_ofs[N_NODES] = base;      // == E (tail parts are 0)
}

__global__ void fill_kernel(const float* __restrict__ vals,
                            const int* __restrict__ row,
                            const int* __restrict__ col, int E) {
    int e = blockIdx.x * blockDim.x + threadIdx.x;
    if (e < E) {
        int p = atomicAdd(&g_cnt[row[e]], 1);
        g_csr_col[p] = col[e];
        g_csr_val[p] = vals[e];
    }
}

// ---------------------------------------------------------------------------
// Gather + bf16 split: one node per 128 threads (4 nodes / 512-thread block).
// ---------------------------------------------------------------------------
__global__ __launch_bounds__(512) void gather_split_kernel(const float* __restrict__ x)
{
    const int node = blockIdx.x * 4 + (threadIdx.x >> 7);
    if (node >= N_NODES) return;
    const int f4 = threadIdx.x & 127;

    const int beg = g_ofs[node];
    const int end = g_ofs[node + 1];

    float4 acc = make_float4(0.f, 0.f, 0.f, 0.f);
    for (int p = beg; p < end; p++) {
        const int   c = g_csr_col[p];          // warp-uniform (broadcast)
        const float v = g_csr_val[p];
        float4 xv = reinterpret_cast<const float4*>(x + (size_t)c * N_IN)[f4];
        acc.x += v * xv.x; acc.y += v * xv.y;
        acc.z += v * xv.z; acc.w += v * xv.w;
    }

    uint32_t h0, h1, l0, l1;
    split4(acc, h0, h1, l0, l1);
    uint2* hp = reinterpret_cast<uint2*>(g_Ahi + (size_t)node * N_IN) + f4;
    uint2* lp = reinterpret_cast<uint2*>(g_Alo + (size_t)node * N_IN) + f4;
    *hp = make_uint2(h0, h1);
    *lp = make_uint2(l0, l1);
}

// ---------------------------------------------------------------------------
// W split
// ---------------------------------------------------------------------------
__global__ void split_w_kernel(const float* __restrict__ W) {
    const int n4 = (N_OUT * N_IN) / 4;
    uint32_t* hi = reinterpret_cast<uint32_t*>(g_Whi);
    uint32_t* lo = reinterpret_cast<uint32_t*>(g_Wlo);
    const float4* src = reinterpret_cast<const float4*>(W);
    for (int i = blockIdx.x * blockDim.x + threadIdx.x; i < n4;
         i += gridDim.x * blockDim.x) {
        uint32_t h0, h1, l0, l1;
        split4(src[i], h0, h1, l0, l1);
        hi[i * 2] = h0; hi[i * 2 + 1] = h1;
        lo[i * 2] = l0; lo[i * 2 + 1] = l1;
    }
}

// ---------------------------------------------------------------------------
// GEMM: out = agg @ W^T via mma.sync bf16x3 (hi/lo split, fp32 accum)
// Block tile 128x128, BK=64; 8 warps (2m x 4n), warp tile 64x32.
// 2-stage double-buffered cp.async pipeline (2 x 64 KB smem, 1 CTA/SM):
// prefetch chunk c+1 during compute of chunk c (wait_group 1).
// ---------------------------------------------------------------------------
#define GBM 128
#define GBN 128
#define NCHUNK (N_IN / 64)     // 8

#define OFF_AHI 0
#define OFF_ALO 16384
#define OFF_BHI 32768
#define OFF_BLO 49152
#define STAGE_SZ 65536
#define GEMM_SMEM (2 * STAGE_SZ)   // 128 KB

__global__ __launch_bounds__(256, 1) void mma_gemm_kernel(float* __restrict__ out)
{
    extern __shared__ __align__(1024) char smem[];
    const uint32_t sbase = smem_u32(smem);
    const int tid = threadIdx.x;
    const int wid = tid >> 5;
    const int lane = tid & 31;
    const int wm = wid >> 2;            // 0..1 : rows wm*64
    const int wn = wid & 3;             // 0..3 : cols wn*32
    const int m0 = blockIdx.y * GBM;
    const int n0 = blockIdx.x * GBN;

    const int r = tid >> 1;             // 0..127
    const int h = tid & 1;              // 0..1
    const char* srcA_hi = (const char*)(g_Ahi + (size_t)(m0 + r) * N_IN);
    const char* srcA_lo = (const char*)(g_Alo + (size_t)(m0 + r) * N_IN);
    const char* srcB_hi = (const char*)(g_Whi + (size_t)(n0 + r) * N_IN);
    const char* srcB_lo = (const char*)(g_Wlo + (size_t)(n0 + r) * N_IN);

    // Issue one chunk's 4 tiles into the given stage, then commit the group.
    auto load_chunk = [&](int chunk, uint32_t stg) {
        const int cbyte = chunk * 128;
        #pragma unroll
        for (int jj = 0; jj < 4; jj++) {
            const int j = h * 4 + jj;
            const uint32_t dst = sw128((uint32_t)(r * 128 + j * 16));
            const int so = cbyte + j * 16;
            cp_async16(sbase + stg + OFF_AHI + dst, srcA_hi + so);
            cp_async16(sbase + stg + OFF_ALO + dst, srcA_lo + so);
            cp_async16(sbase + stg + OFF_BHI + dst, srcB_hi + so);
            cp_async16(sbase + stg + OFF_BLO + dst, srcB_lo + so);
        }
        asm volatile("cp.async.commit_group;" ::: "memory");
    };

    float acc[4][4][4];
    #pragma unroll
    for (int i = 0; i < 4; i++)
        #pragma unroll
        for (int j = 0; j < 4; j++)
            #pragma unroll
            for (int k = 0; k < 4; k++) acc[i][j][k] = 0.f;

    load_chunk(0, 0);   // prologue

    for (int chunk = 0; chunk < NCHUNK; chunk++) {
        const uint32_t stg = (uint32_t)(chunk & 1) * STAGE_SZ;

        if (chunk + 1 < NCHUNK) {
            load_chunk(chunk + 1, (uint32_t)((chunk + 1) & 1) * STAGE_SZ);
            asm volatile("cp.async.wait_group 1;" ::: "memory");  // chunk c landed
        } else {
            asm volatile("cp.async.wait_group 0;" ::: "memory");
        }
        __syncthreads();

        #pragma unroll
        for (int ks = 0; ks < 4; ks++) {
            uint32_t a[4][4], bh[4][2], bl[4][2];

            // A-hi fragments
            #pragma unroll
            for (int mf = 0; mf < 4; mf++) {
                uint32_t off = (uint32_t)((wm * 64 + mf * 16 +
                               ((lane >> 3) & 1) * 8 + (lane & 7)) * 128
                               + ks * 32 + (lane >> 4) * 16);
                ldsm_x4(a[mf][0], a[mf][1], a[mf][2], a[mf][3],
                        sbase + stg + OFF_AHI + sw128(off));
            }
            // B-hi fragments
            #pragma unroll
            for (int nf2 = 0; nf2 < 2; nf2++) {
                uint32_t off = (uint32_t)((wn * 32 + nf2 * 16 +
                               ((lane >> 4) & 1) * 8 + (lane & 7)) * 128
                               + ks * 32 + ((lane >> 3) & 1) * 16);
                ldsm_x4(bh[nf2 * 2][0], bh[nf2 * 2][1],
                        bh[nf2 * 2 + 1][0], bh[nf2 * 2 + 1][1],
                        sbase + stg + OFF_BHI + sw128(off));
            }
            // chain 1: hi * hi
            #pragma unroll
            for (int mf = 0; mf < 4; mf++)
                #pragma unroll
                for (int nf = 0; nf < 4; nf++)
                    mma_bf16(acc[mf][nf][0], acc[mf][nf][1],
                             acc[mf][nf][2], acc[mf][nf][3],
                             a[mf][0], a[mf][1], a[mf][2], a[mf][3],
                             bh[nf][0], bh[nf][1]);

            // B-lo fragments
            #pragma unroll
            for (int nf2 = 0; nf2 < 2; nf2++) {
                uint32_t off = (uint32_t)((wn * 32 + nf2 * 16 +
                               ((lane >> 4) & 1) * 8 + (lane & 7)) * 128
                               + ks * 32 + ((lane >> 3) & 1) * 16);
                ldsm_x4(bl[nf2 * 2][0], bl[nf2 * 2][1],
                        bl[nf2 * 2 + 1][0], bl[nf2 * 2 + 1][1],
                        sbase + stg + OFF_BLO + sw128(off));
            }
            // chain 2: hi * lo  (reuse A-hi regs)
            #pragma unroll
            for (int mf = 0; mf < 4; mf++)
                #pragma unroll
                for (int nf = 0; nf < 4; nf++)
                    mma_bf16(acc[mf][nf][0], acc[mf][nf][1],
                             acc[mf][nf][2], acc[mf][nf][3],
                             a[mf][0], a[mf][1], a[mf][2], a[mf][3],
                             bl[nf][0], bl[nf][1]);

            // A-lo fragments (overwrite a)
            #pragma unroll
            for (int mf = 0; mf < 4; mf++) {
                uint32_t off = (uint32_t)((wm * 64 + mf * 16 +
                               ((lane >> 3) & 1) * 8 + (lane & 7)) * 128
                               + ks * 32 + (lane >> 4) * 16);
                ldsm_x4(a[mf][0], a[mf][1], a[mf][2], a[mf][3],
                        sbase + stg + OFF_ALO + sw128(off));
            }
            // chain 3: lo * hi  (reuse B-hi regs)
            #pragma unroll
            for (int mf = 0; mf < 4; mf++)
                #pragma unroll
                for (int nf = 0; nf < 4; nf++)
                    mma_bf16(acc[mf][nf][0], acc[mf][nf][1],
                             acc[mf][nf][2], acc[mf][nf][3],
                             a[mf][0], a[mf][1], a[mf][2], a[mf][3],
                             bh[nf][0], bh[nf][1]);
        }
        __syncthreads();   // all warps done with stage before it is overwritten
    }

    // ---- epilogue ----
    #pragma unroll
    for (int mf = 0; mf < 4; mf++) {
        const int mrow = m0 + wm * 64 + mf * 16 + (lane >> 2);
        #pragma unroll
        for (int nf = 0; nf < 4; nf++) {
            const int ncol = n0 + wn * 32 + nf * 8 + (lane & 3) * 2;
            if (mrow < N_NODES) {
                float2* p = reinterpret_cast<float2*>(out + (size_t)mrow * N_OUT + ncol);
                *p = make_float2(acc[mf][nf][0], acc[mf][nf][1]);
            }
            if (mrow + 8 < N_NODES) {
                float2* p = reinterpret_cast<float2*>(out + (size_t)(mrow + 8) * N_OUT + ncol);
                *p = make_float2(acc[mf][nf][2], acc[mf][nf][3]);
            }
        }
    }
}

// ---------------------------------------------------------------------------
// Launch
// ---------------------------------------------------------------------------
extern "C" void kernel_launch(void* const* d_in, const int* in_sizes, int n_in,
                              void* d_out, int out_size)
{
    const float* x    = (const float*)d_in[0];
    const float* vals = (const float*)d_in[1];
    const float* W    = (const float*)d_in[2];
    const int*   row  = (const int*)d_in[3];
    const int*   col  = (const int*)d_in[4];
    float*       out  = (float*)d_out;

    int E = in_sizes[1];

    static bool s_init = false;
    if (!s_init) {
        cudaFuncSetAttribute(mma_gemm_kernel,
                             cudaFuncAttributeMaxDynamicSharedMemorySize, GEMM_SMEM);
        s_init = true;
    }

    zero_cnt_kernel<<<(N_NODES + 511) / 512, 512>>>();
    hist_kernel<<<(E + 511) / 512, 512>>>(row, E);
    scan_kernel<<<1, 1024>>>();
    fill_kernel<<<(E + 511) / 512, 512>>>(vals, row, col, E);
    gather_split_kernel<<<(N_NODES + 3) / 4, 512>>>(x);
    split_w_kernel<<<256, 256>>>(W);

    dim3 grid(N_OUT / GBN, M_PAD / GBM);   // (4, 157)
    mma_gemm_kernel<<<grid, 256, GEMM_SMEM>>>(out);
}

// round 13
// speedup vs baseline: 1.0667x; 1.0667x over previous
#include <cuda_runtime.h>
#include <cuda_bf16.h>
#include <cstdint>

#define N_NODES 20000
#define N_EDGES 160000
#define N_IN    512
#define N_OUT   512
#define M_PAD   20096            // 157 * 128

// Static device scratch (no runtime allocation; zero-initialized at load)
__device__ __nv_bfloat16  g_Ahi[(size_t)M_PAD * N_IN];   // 20.6 MB (padding rows stay 0)
__device__ __nv_bfloat16  g_Alo[(size_t)M_PAD * N_IN];   // 20.6 MB
__device__ __nv_bfloat16  g_Whi[(size_t)N_OUT * N_IN];
__device__ __nv_bfloat16  g_Wlo[(size_t)N_OUT * N_IN];
__device__ int            g_cnt[N_NODES];                // histogram, then fill cursor
__device__ int            g_ofs[N_NODES + 1];            // CSR row offsets
__device__ int            g_csr_col[N_EDGES];
__device__ float          g_csr_val[N_EDGES];

// ---------------------------------------------------------------------------
// Helpers
// ---------------------------------------------------------------------------
__device__ __forceinline__ uint32_t smem_u32(const void* p) {
    uint32_t a;
    asm("{ .reg .u64 t; cvta.to.shared.u64 t, %1; cvt.u32.u64 %0, t; }"
        : "=r"(a) : "l"(p));
    return a;
}

// Split 4 fp32 into bf16 hi (rn) and bf16 lo = bf16(a - float(hi)); packed pairs
__device__ __forceinline__ void split4(float4 f, uint32_t& hi0, uint32_t& hi1,
                                       uint32_t& lo0, uint32_t& lo1) {
    __nv_bfloat16 hx = __float2bfloat16(f.x);
    __nv_bfloat16 hy = __float2bfloat16(f.y);
    __nv_bfloat16 hz = __float2bfloat16(f.z);
    __nv_bfloat16 hw = __float2bfloat16(f.w);
    __nv_bfloat16 lx = __float2bfloat16(f.x - __bfloat162float(hx));
    __nv_bfloat16 ly = __float2bfloat16(f.y - __bfloat162float(hy));
    __nv_bfloat16 lz = __float2bfloat16(f.z - __bfloat162float(hz));
    __nv_bfloat16 lw = __float2bfloat16(f.w - __bfloat162float(hw));
    __nv_bfloat162 H0 = __halves2bfloat162(hx, hy);
    __nv_bfloat162 H1 = __halves2bfloat162(hz, hw);
    __nv_bfloat162 L0 = __halves2bfloat162(lx, ly);
    __nv_bfloat162 L1 = __halves2bfloat162(lz, lw);
    hi0 = *reinterpret_cast<uint32_t*>(&H0);
    hi1 = *reinterpret_cast<uint32_t*>(&H1);
    lo0 = *reinterpret_cast<uint32_t*>(&L0);
    lo1 = *reinterpret_cast<uint32_t*>(&L1);
}

__device__ __forceinline__ void cp_async16(uint32_t smem_addr, const void* gptr) {
    asm volatile("cp.async.cg.shared.global [%0], [%1], 16;"
                 :: "r"(smem_addr), "l"(gptr) : "memory");
}

__device__ __forceinline__ void ldsm_x4(uint32_t& r0, uint32_t& r1,
                                        uint32_t& r2, uint32_t& r3, uint32_t addr) {
    asm volatile("ldmatrix.sync.aligned.m8n8.x4.shared.b16 {%0,%1,%2,%3}, [%4];"
                 : "=r"(r0), "=r"(r1), "=r"(r2), "=r"(r3) : "r"(addr));
}

__device__ __forceinline__ void mma_bf16(float& c0, float& c1, float& c2, float& c3,
                                         uint32_t a0, uint32_t a1, uint32_t a2, uint32_t a3,
                                         uint32_t b0, uint32_t b1) {
    asm volatile(
        "mma.sync.aligned.m16n8k16.row.col.f32.bf16.bf16.f32 "
        "{%0,%1,%2,%3}, {%4,%5,%6,%7}, {%8,%9}, {%0,%1,%2,%3};"
        : "+f"(c0), "+f"(c1), "+f"(c2), "+f"(c3)
        : "r"(a0), "r"(a1), "r"(a2), "r"(a3), "r"(b0), "r"(b1));
}

// SW64 swizzle for 64-byte rows (atom: 8 rows x 64B)
__device__ __forceinline__ uint32_t sw64(uint32_t off) {
    return off ^ ((off >> 3) & 0x30);
}

// ---------------------------------------------------------------------------
// CSR build: zero counts -> histogram -> scan -> fill
// ---------------------------------------------------------------------------
__global__ void zero_cnt_kernel() {
    int i = blockIdx.x * blockDim.x + threadIdx.x;
    if (i < N_NODES) g_cnt[i] = 0;
}

__global__ void hist_kernel(const int* __restrict__ row, int E) {
    int e = blockIdx.x * blockDim.x + threadIdx.x;
    if (e < E) atomicAdd(&g_cnt[row[e]], 1);
}

// Single-block exclusive scan of g_cnt -> g_ofs; re-init g_cnt as fill cursor.
__global__ __launch_bounds__(1024) void scan_kernel() {
    __shared__ int s[1024];
    const int t = threadIdx.x;
    const int PER = 20;                        // 1024*20 = 20480 >= N_NODES
    const int beg = t * PER;
    const int end = min(beg + PER, N_NODES);

    int part = 0;
    for (int i = beg; i < end; i++) part += g_cnt[i];
    s[t] = part;
    __syncthreads();
    for (int off = 1; off < 1024; off <<= 1) {
        int v = (t >= off) ? s[t - off] : 0;
        __syncthreads();
        s[t] += v;
        __syncthreads();
    }
    int base = s[t] - part;                    // exclusive prefix
    for (int i = beg; i < end; i++) {
        int c = g_cnt[i];
        g_ofs[i] = base;
        g_cnt[i] = base;                       // cursor for fill
        base += c;
    }
    if (t == 1023) g_ofs[N_NODES] = base;      // == E (tail parts are 0)
}

__global__ void fill_kernel(const float* __restrict__ vals,
                            const int* __restrict__ row,
                            const int* __restrict__ col, int E) {
    int e = blockIdx.x * blockDim.x + threadIdx.x;
    if (e < E) {
        int p = atomicAdd(&g_cnt[row[e]], 1);
        g_csr_col[p] = col[e];
        g_csr_val[p] = vals[e];
    }
}

// ---------------------------------------------------------------------------
// Gather + bf16 split: one node per 128 threads (4 nodes / 512-thread block).
// ---------------------------------------------------------------------------
__global__ __launch_bounds__(512) void gather_split_kernel(const float* __restrict__ x)
{
    const int node = blockIdx.x * 4 + (threadIdx.x >> 7);
    if (node >= N_NODES) return;
    const int f4 = threadIdx.x & 127;

    const int beg = g_ofs[node];
    const int end = g_ofs[node + 1];

    float4 acc = make_float4(0.f, 0.f, 0.f, 0.f);
    for (int p = beg; p < end; p++) {
        const int   c = g_csr_col[p];          // warp-uniform (broadcast)
        const float v = g_csr_val[p];
        float4 xv = reinterpret_cast<const float4*>(x + (size_t)c * N_IN)[f4];
        acc.x += v * xv.x; acc.y += v * xv.y;
        acc.z += v * xv.z; acc.w += v * xv.w;
    }

    uint32_t h0, h1, l0, l1;
    split4(acc, h0, h1, l0, l1);
    uint2* hp = reinterpret_cast<uint2*>(g_Ahi + (size_t)node * N_IN) + f4;
    uint2* lp = reinterpret_cast<uint2*>(g_Alo + (size_t)node * N_IN) + f4;
    *hp = make_uint2(h0, h1);
    *lp = make_uint2(l0, l1);
}

// ---------------------------------------------------------------------------
// W split
// ---------------------------------------------------------------------------
__global__ void split_w_kernel(const float* __restrict__ W) {
    const int n4 = (N_OUT * N_IN) / 4;
    uint32_t* hi = reinterpret_cast<uint32_t*>(g_Whi);
    uint32_t* lo = reinterpret_cast<uint32_t*>(g_Wlo);
    const float4* src = reinterpret_cast<const float4*>(W);
    for (int i = blockIdx.x * blockDim.x + threadIdx.x; i < n4;
         i += gridDim.x * blockDim.x) {
        uint32_t h0, h1, l0, l1;
        split4(src[i], h0, h1, l0, l1);
        hi[i * 2] = h0; hi[i * 2 + 1] = h1;
        lo[i * 2] = l0; lo[i * 2 + 1] = l1;
    }
}

// ---------------------------------------------------------------------------
// GEMM: out = agg @ W^T via mma.sync bf16x3 (hi/lo split, fp32 accum)
// Block tile 128x128; 8 warps (2m x 4n), warp tile 64x32.
// K=32 double-buffered stages (2 x 32 KB) -> 64 KB smem -> 2 CTAs/SM:
// restores 16-warp/SM latency hiding AND overlaps loads with compute.
// Rows are 64B wide -> SW64 swizzle (conflict-free ldmatrix verified).
// ---------------------------------------------------------------------------
#define GBM 128
#define GBN 128
#define NSTEP (N_IN / 32)      // 16 K-steps of 32

#define T_AHI 0
#define T_ALO 8192
#define T_BHI 16384
#define T_BLO 24576
#define STAGE_SZ 32768
#define GEMM_SMEM (2 * STAGE_SZ)   // 64 KB

__global__ __launch_bounds__(256, 2) void mma_gemm_kernel(float* __restrict__ out)
{
    extern __shared__ __align__(1024) char smem[];
    const uint32_t sbase = smem_u32(smem);
    const int tid = threadIdx.x;
    const int wid = tid >> 5;
    const int lane = tid & 31;
    const int wm = wid >> 2;            // 0..1 : rows wm*64
    const int wn = wid & 3;             // 0..3 : cols wn*32
    const int m0 = blockIdx.y * GBM;
    const int n0 = blockIdx.x * GBN;

    const int r = tid >> 1;             // 0..127 (tile row this thread loads)
    const int h = tid & 1;              // 0..1   (which 32B half of the 64B row)
    const char* srcA_hi = (const char*)(g_Ahi + (size_t)(m0 + r) * N_IN);
    const char* srcA_lo = (const char*)(g_Alo + (size_t)(m0 + r) * N_IN);
    const char* srcB_hi = (const char*)(g_Whi + (size_t)(n0 + r) * N_IN);
    const char* srcB_lo = (const char*)(g_Wlo + (size_t)(n0 + r) * N_IN);

    // Load one K32 step (4 tiles x 128 rows x 64B) into a stage; commit group.
    auto load_step = [&](int step, uint32_t stg) {
        const int cbyte = step * 64;                 // 32 bf16 = 64B per row
        #pragma unroll
        for (int jj = 0; jj < 2; jj++) {
            const int j = h * 2 + jj;                // 16B chunk 0..3
            const uint32_t dst = sw64((uint32_t)(r * 64 + j * 16));
            const int so = cbyte + j * 16;
            cp_async16(sbase + stg + T_AHI + dst, srcA_hi + so);
            cp_async16(sbase + stg + T_ALO + dst, srcA_lo + so);
            cp_async16(sbase + stg + T_BHI + dst, srcB_hi + so);
            cp_async16(sbase + stg + T_BLO + dst, srcB_lo + so);
        }
        asm volatile("cp.async.commit_group;" ::: "memory");
    };

    float acc[4][4][4];
    #pragma unroll
    for (int i = 0; i < 4; i++)
        #pragma unroll
        for (int j = 0; j < 4; j++)
            #pragma unroll
            for (int k = 0; k < 4; k++) acc[i][j][k] = 0.f;

    load_step(0, 0);   // prologue

    for (int s = 0; s < NSTEP; s++) {
        const uint32_t stg = (uint32_t)(s & 1) * STAGE_SZ;

        if (s + 1 < NSTEP) {
            load_step(s + 1, (uint32_t)((s + 1) & 1) * STAGE_SZ);
            asm volatile("cp.async.wait_group 1;" ::: "memory");  // step s landed
        } else {
            asm volatile("cp.async.wait_group 0;" ::: "memory");
        }
        __syncthreads();

        #pragma unroll
        for (int ks = 0; ks < 2; ks++) {     // two K16 sub-steps per stage
            uint32_t a[4][4], bh[4][2], bl[4][2];

            // A-hi fragments
            #pragma unroll
            for (int mf = 0; mf < 4; mf++) {
                uint32_t off = (uint32_t)((wm * 64 + mf * 16 +
                               ((lane >> 3) & 1) * 8 + (lane & 7)) * 64
                               + ks * 32 + (lane >> 4) * 16);
                ldsm_x4(a[mf][0], a[mf][1], a[mf][2], a[mf][3],
                        sbase + stg + T_AHI + sw64(off));
            }
            // B-hi fragments
            #pragma unroll
            for (int nf2 = 0; nf2 < 2; nf2++) {
                uint32_t off = (uint32_t)((wn * 32 + nf2 * 16 +
                               ((lane >> 4) & 1) * 8 + (lane & 7)) * 64
                               + ks * 32 + ((lane >> 3) & 1) * 16);
                ldsm_x4(bh[nf2 * 2][0], bh[nf2 * 2][1],
                        bh[nf2 * 2 + 1][0], bh[nf2 * 2 + 1][1],
                        sbase + stg + T_BHI + sw64(off));
            }
            // chain 1: hi * hi
            #pragma unroll
            for (int mf = 0; mf < 4; mf++)
                #pragma unroll
                for (int nf = 0; nf < 4; nf++)
                    mma_bf16(acc[mf][nf][0], acc[mf][nf][1],
                             acc[mf][nf][2], acc[mf][nf][3],
                             a[mf][0], a[mf][1], a[mf][2], a[mf][3],
                             bh[nf][0], bh[nf][1]);

            // B-lo fragments
            #pragma unroll
            for (int nf2 = 0; nf2 < 2; nf2++) {
                uint32_t off = (uint32_t)((wn * 32 + nf2 * 16 +
                               ((lane >> 4) & 1) * 8 + (lane & 7)) * 64
                               + ks * 32 + ((lane >> 3) & 1) * 16);
                ldsm_x4(bl[nf2 * 2][0], bl[nf2 * 2][1],
                        bl[nf2 * 2 + 1][0], bl[nf2 * 2 + 1][1],
                        sbase + stg + T_BLO + sw64(off));
            }
            // chain 2: hi * lo  (reuse A-hi regs)
            #pragma unroll
            for (int mf = 0; mf < 4; mf++)
                #pragma unroll
                for (int nf = 0; nf < 4; nf++)
                    mma_bf16(acc[mf][nf][0], acc[mf][nf][1],
                             acc[mf][nf][2], acc[mf][nf][3],
                             a[mf][0], a[mf][1], a[mf][2], a[mf][3],
                             bl[nf][0], bl[nf][1]);

            // A-lo fragments (overwrite a)
            #pragma unroll
            for (int mf = 0; mf < 4; mf++) {
                uint32_t off = (uint32_t)((wm * 64 + mf * 16 +
                               ((lane >> 3) & 1) * 8 + (lane & 7)) * 64
                               + ks * 32 + (lane >> 4) * 16);
                ldsm_x4(a[mf][0], a[mf][1], a[mf][2], a[mf][3],
                        sbase + stg + T_ALO + sw64(off));
            }
            // chain 3: lo * hi  (reuse B-hi regs)
            #pragma unroll
            for (int mf = 0; mf < 4; mf++)
                #pragma unroll
                for (int nf = 0; nf < 4; nf++)
                    mma_bf16(acc[mf][nf][0], acc[mf][nf][1],
                             acc[mf][nf][2], acc[mf][nf][3],
                             a[mf][0], a[mf][1], a[mf][2], a[mf][3],
                             bh[nf][0], bh[nf][1]);
        }
        __syncthreads();   // stage fully consumed before it is overwritten
    }

    // ---- epilogue ----
    #pragma unroll
    for (int mf = 0; mf < 4; mf++) {
        const int mrow = m0 + wm * 64 + mf * 16 + (lane >> 2);
        #pragma unroll
        for (int nf = 0; nf < 4; nf++) {
            const int ncol = n0 + wn * 32 + nf * 8 + (lane & 3) * 2;
            if (mrow < N_NODES) {
                float2* p = reinterpret_cast<float2*>(out + (size_t)mrow * N_OUT + ncol);
                *p = make_float2(acc[mf][nf][0], acc[mf][nf][1]);
            }
            if (mrow + 8 < N_NODES) {
                float2* p = reinterpret_cast<float2*>(out + (size_t)(mrow + 8) * N_OUT + ncol);
                *p = make_float2(acc[mf][nf][2], acc[mf][nf][3]);
            }
        }
    }
}

// ---------------------------------------------------------------------------
// Launch
// ---------------------------------------------------------------------------
extern "C" void kernel_launch(void* const* d_in, const int* in_sizes, int n_in,
                              void* d_out, int out_size)
{
    const float* x    = (const float*)d_in[0];
    const float* vals = (const float*)d_in[1];
    const float* W    = (const float*)d_in[2];
    const int*   row  = (const int*)d_in[3];
    const int*   col  = (const int*)d_in[4];
    float*       out  = (float*)d_out;

    int E = in_sizes[1];

    static bool s_init = false;
    if (!s_init) {
        cudaFuncSetAttribute(mma_gemm_kernel,
                             cudaFuncAttributeMaxDynamicSharedMemorySize, GEMM_SMEM);
        s_init = true;
    }

    zero_cnt_kernel<<<(N_NODES + 511) / 512, 512>>>();
    hist_kernel<<<(E + 511) / 512, 512>>>(row, E);
    scan_kernel<<<1, 1024>>>();
    fill_kernel<<<(E + 511) / 512, 512>>>(vals, row, col, E);
    gather_split_kernel<<<(N_NODES + 3) / 4, 512>>>(x);
    split_w_kernel<<<256, 256>>>(W);

    dim3 grid(N_OUT / GBN, M_PAD / GBM);   // (4, 157)
    mma_gemm_kernel<<<grid, 256, GEMM_SMEM>>>(out);
}

// round 14
// speedup vs baseline: 1.2763x; 1.1965x over previous
#include <cuda_runtime.h>
#include <cuda_fp16.h>
#include <cstdint>

#define N_NODES 20000
#define N_EDGES 160000
#define N_IN    512
#define N_OUT   512
#define M_PAD   20096            // 157 * 128

// Static device scratch (no runtime allocation; zero-initialized at load)
__device__ __half         g_Ahi[(size_t)M_PAD * N_IN];   // 20.6 MB (padding rows stay 0)
__device__ __half         g_Alo[(size_t)M_PAD * N_IN];   // 20.6 MB
__device__ __half         g_Whi[(size_t)N_OUT * N_IN];   // 0.5 MB
__device__ int            g_cnt[N_NODES];                // histogram, then fill cursor
__device__ int            g_ofs[N_NODES + 1];            // CSR row offsets
__device__ int            g_csr_col[N_EDGES];
__device__ float          g_csr_val[N_EDGES];

// ---------------------------------------------------------------------------
// Helpers
// ---------------------------------------------------------------------------
__device__ __forceinline__ uint32_t smem_u32(const void* p) {
    uint32_t a;
    asm("{ .reg .u64 t; cvta.to.shared.u64 t, %1; cvt.u32.u64 %0, t; }"
        : "=r"(a) : "l"(p));
    return a;
}

// Split 4 fp32 into fp16 hi (rn) and fp16 lo = fp16(a - float(hi)); packed pairs
__device__ __forceinline__ void split4h(float4 f, uint32_t& hi0, uint32_t& hi1,
                                        uint32_t& lo0, uint32_t& lo1) {
    __half hx = __float2half_rn(f.x);
    __half hy = __float2half_rn(f.y);
    __half hz = __float2half_rn(f.z);
    __half hw = __float2half_rn(f.w);
    __half lx = __float2half_rn(f.x - __half2float(hx));
    __half ly = __float2half_rn(f.y - __half2float(hy));
    __half lz = __float2half_rn(f.z - __half2float(hz));
    __half lw = __float2half_rn(f.w - __half2float(hw));
    __half2 H0 = __halves2half2(hx, hy);
    __half2 H1 = __halves2half2(hz, hw);
    __half2 L0 = __halves2half2(lx, ly);
    __half2 L1 = __halves2half2(lz, lw);
    hi0 = *reinterpret_cast<uint32_t*>(&H0);
    hi1 = *reinterpret_cast<uint32_t*>(&H1);
    lo0 = *reinterpret_cast<uint32_t*>(&L0);
    lo1 = *reinterpret_cast<uint32_t*>(&L1);
}

__device__ __forceinline__ void cp_async16(uint32_t smem_addr, const void* gptr) {
    asm volatile("cp.async.cg.shared.global [%0], [%1], 16;"
                 :: "r"(smem_addr), "l"(gptr) : "memory");
}

__device__ __forceinline__ void ldsm_x4(uint32_t& r0, uint32_t& r1,
                                        uint32_t& r2, uint32_t& r3, uint32_t addr) {
    asm volatile("ldmatrix.sync.aligned.m8n8.x4.shared.b16 {%0,%1,%2,%3}, [%4];"
                 : "=r"(r0), "=r"(r1), "=r"(r2), "=r"(r3) : "r"(addr));
}

__device__ __forceinline__ void mma_f16(float& c0, float& c1, float& c2, float& c3,
                                        uint32_t a0, uint32_t a1, uint32_t a2, uint32_t a3,
                                        uint32_t b0, uint32_t b1) {
    asm volatile(
        "mma.sync.aligned.m16n8k16.row.col.f32.f16.f16.f32 "
        "{%0,%1,%2,%3}, {%4,%5,%6,%7}, {%8,%9}, {%0,%1,%2,%3};"
        : "+f"(c0), "+f"(c1), "+f"(c2), "+f"(c3)
        : "r"(a0), "r"(a1), "r"(a2), "r"(a3), "r"(b0), "r"(b1));
}

// SW64 swizzle for 64-byte rows (atom: 8 rows x 64B)
__device__ __forceinline__ uint32_t sw64(uint32_t off) {
    return off ^ ((off >> 3) & 0x30);
}

// ---------------------------------------------------------------------------
// CSR build: zero counts -> histogram -> scan -> fill
// ---------------------------------------------------------------------------
__global__ void zero_cnt_kernel() {
    int i = blockIdx.x * blockDim.x + threadIdx.x;
    if (i < N_NODES) g_cnt[i] = 0;
}

__global__ void hist_kernel(const int* __restrict__ row, int E) {
    int e = blockIdx.x * blockDim.x + threadIdx.x;
    if (e < E) atomicAdd(&g_cnt[row[e]], 1);
}

// Single-block exclusive scan of g_cnt -> g_ofs; re-init g_cnt as fill cursor.
__global__ __launch_bounds__(1024) void scan_kernel() {
    __shared__ int s[1024];
    const int t = threadIdx.x;
    const int PER = 20;                        // 1024*20 = 20480 >= N_NODES
    const int beg = t * PER;
    const int end = min(beg + PER, N_NODES);

    int part = 0;
    for (int i = beg; i < end; i++) part += g_cnt[i];
    s[t] = part;
    __syncthreads();
    for (int off = 1; off < 1024; off <<= 1) {
        int v = (t >= off) ? s[t - off] : 0;
        __syncthreads();
        s[t] += v;
        __syncthreads();
    }
    int base = s[t] - part;                    // exclusive prefix
    for (int i = beg; i < end; i++) {
        int c = g_cnt[i];
        g_ofs[i] = base;
        g_cnt[i] = base;                       // cursor for fill
        base += c;
    }
    if (t == 1023) g_ofs[N_NODES] = base;      // == E (tail parts are 0)
}

__global__ void fill_kernel(const float* __restrict__ vals,
                            const int* __restrict__ row,
                            const int* __restrict__ col, int E) {
    int e = blockIdx.x * blockDim.x + threadIdx.x;
    if (e < E) {
        int p = atomicAdd(&g_cnt[row[e]], 1);
        g_csr_col[p] = col[e];
        g_csr_val[p] = vals[e];
    }
}

// ---------------------------------------------------------------------------
// Gather + fp16 split: one node per 128 threads (4 nodes / 512-thread block).
// ---------------------------------------------------------------------------
__global__ __launch_bounds__(512) void gather_split_kernel(const float* __restrict__ x)
{
    const int node = blockIdx.x * 4 + (threadIdx.x >> 7);
    if (node >= N_NODES) return;
    const int f4 = threadIdx.x & 127;

    const int beg = g_ofs[node];
    const int end = g_ofs[node + 1];

    float4 acc = make_float4(0.f, 0.f, 0.f, 0.f);
    for (int p = beg; p < end; p++) {
        const int   c = g_csr_col[p];          // warp-uniform (broadcast)
        const float v = g_csr_val[p];
        float4 xv = reinterpret_cast<const float4*>(x + (size_t)c * N_IN)[f4];
        acc.x += v * xv.x; acc.y += v * xv.y;
        acc.z += v * xv.z; acc.w += v * xv.w;
    }

    uint32_t h0, h1, l0, l1;
    split4h(acc, h0, h1, l0, l1);
    uint2* hp = reinterpret_cast<uint2*>(g_Ahi + (size_t)node * N_IN) + f4;
    uint2* lp = reinterpret_cast<uint2*>(g_Alo + (size_t)node * N_IN) + f4;
    *hp = make_uint2(h0, h1);
    *lp = make_uint2(l0, l1);
}

// ---------------------------------------------------------------------------
// W split: only hi needed (2-chain corrects A's rounding; B's ~2^-12 remains)
// ---------------------------------------------------------------------------
__global__ void split_w_kernel(const float* __restrict__ W) {
    const int n4 = (N_OUT * N_IN) / 4;
    uint32_t* hi = reinterpret_cast<uint32_t*>(g_Whi);
    const float4* src = reinterpret_cast<const float4*>(W);
    for (int i = blockIdx.x * blockDim.x + threadIdx.x; i < n4;
         i += gridDim.x * blockDim.x) {
        float4 f = src[i];
        __half2 H0 = __halves2half2(__float2half_rn(f.x), __float2half_rn(f.y));
        __half2 H1 = __halves2half2(__float2half_rn(f.z), __float2half_rn(f.w));
        hi[i * 2]     = *reinterpret_cast<uint32_t*>(&H0);
        hi[i * 2 + 1] = *reinterpret_cast<uint32_t*>(&H1);
    }
}

// ---------------------------------------------------------------------------
// GEMM: out = agg @ W^T via mma.sync fp16 x2 (hi/lo split A, fp32 accum)
// D = Ahi*Bhi + Alo*Bhi. Block tile 128x128; 8 warps (2m x 4n), warp 64x32.
// K=32 double-buffered stages (2 x 24 KB = 48 KB) -> 2 CTAs/SM.
// ---------------------------------------------------------------------------
#define GBM 128
#define GBN 128
#define NSTEP (N_IN / 32)      // 16 K-steps of 32

#define T_AHI 0
#define T_ALO 8192
#define T_BHI 16384
#define STAGE_SZ 24576
#define GEMM_SMEM (2 * STAGE_SZ)   // 48 KB

__global__ __launch_bounds__(256, 2) void mma_gemm_kernel(float* __restrict__ out)
{
    extern __shared__ __align__(1024) char smem[];
    const uint32_t sbase = smem_u32(smem);
    const int tid = threadIdx.x;
    const int wid = tid >> 5;
    const int lane = tid & 31;
    const int wm = wid >> 2;            // 0..1 : rows wm*64
    const int wn = wid & 3;             // 0..3 : cols wn*32
    const int m0 = blockIdx.y * GBM;
    const int n0 = blockIdx.x * GBN;

    const int r = tid >> 1;             // 0..127 (tile row this thread loads)
    const int h = tid & 1;              // 0..1   (which 32B half of the 64B row)
    const char* srcA_hi = (const char*)(g_Ahi + (size_t)(m0 + r) * N_IN);
    const char* srcA_lo = (const char*)(g_Alo + (size_t)(m0 + r) * N_IN);
    const char* srcB_hi = (const char*)(g_Whi + (size_t)(n0 + r) * N_IN);

    // Load one K32 step (3 tiles x 128 rows x 64B) into a stage; commit group.
    auto load_step = [&](int step, uint32_t stg) {
        const int cbyte = step * 64;                 // 32 fp16 = 64B per row
        #pragma unroll
        for (int jj = 0; jj < 2; jj++) {
            const int j = h * 2 + jj;                // 16B chunk 0..3
            const uint32_t dst = sw64((uint32_t)(r * 64 + j * 16));
            const int so = cbyte + j * 16;
            cp_async16(sbase + stg + T_AHI + dst, srcA_hi + so);
            cp_async16(sbase + stg + T_ALO + dst, srcA_lo + so);
            cp_async16(sbase + stg + T_BHI + dst, srcB_hi + so);
        }
        asm volatile("cp.async.commit_group;" ::: "memory");
    };

    float acc[4][4][4];
    #pragma unroll
    for (int i = 0; i < 4; i++)
        #pragma unroll
        for (int j = 0; j < 4; j++)
            #pragma unroll
            for (int k = 0; k < 4; k++) acc[i][j][k] = 0.f;

    load_step(0, 0);   // prologue

    for (int s = 0; s < NSTEP; s++) {
        const uint32_t stg = (uint32_t)(s & 1) * STAGE_SZ;

        if (s + 1 < NSTEP) {
            load_step(s + 1, (uint32_t)((s + 1) & 1) * STAGE_SZ);
            asm volatile("cp.async.wait_group 1;" ::: "memory");  // step s landed
        } else {
            asm volatile("cp.async.wait_group 0;" ::: "memory");
        }
        __syncthreads();

        #pragma unroll
        for (int ks = 0; ks < 2; ks++) {     // two K16 sub-steps per stage
            uint32_t a[4][4], bh[4][2];

            // A-hi fragments
            #pragma unroll
            for (int mf = 0; mf < 4; mf++) {
                uint32_t off = (uint32_t)((wm * 64 + mf * 16 +
                               ((lane >> 3) & 1) * 8 + (lane & 7)) * 64
                               + ks * 32 + (lane >> 4) * 16);
                ldsm_x4(a[mf][0], a[mf][1], a[mf][2], a[mf][3],
                        sbase + stg + T_AHI + sw64(off));
            }
            // B-hi fragments
            #pragma unroll
            for (int nf2 = 0; nf2 < 2; nf2++) {
                uint32_t off = (uint32_t)((wn * 32 + nf2 * 16 +
                               ((lane >> 4) & 1) * 8 + (lane & 7)) * 64
                               + ks * 32 + ((lane >> 3) & 1) * 16);
                ldsm_x4(bh[nf2 * 2][0], bh[nf2 * 2][1],
                        bh[nf2 * 2 + 1][0], bh[nf2 * 2 + 1][1],
                        sbase + stg + T_BHI + sw64(off));
            }
            // chain 1: Ahi * Bhi
            #pragma unroll
            for (int mf = 0; mf < 4; mf++)
                #pragma unroll
                for (int nf = 0; nf < 4; nf++)
                    mma_f16(acc[mf][nf][0], acc[mf][nf][1],
                            acc[mf][nf][2], acc[mf][nf][3],
                            a[mf][0], a[mf][1], a[mf][2], a[mf][3],
                            bh[nf][0], bh[nf][1]);

            // A-lo fragments (overwrite a)
            #pragma unroll
            for (int mf = 0; mf < 4; mf++) {
                uint32_t off = (uint32_t)((wm * 64 + mf * 16 +
                               ((lane >> 3) & 1) * 8 + (lane & 7)) * 64
                               + ks * 32 + (lane >> 4) * 16);
                ldsm_x4(a[mf][0], a[mf][1], a[mf][2], a[mf][3],
                        sbase + stg + T_ALO + sw64(off));
            }
            // chain 2: Alo * Bhi (reuse B-hi regs)
            #pragma unroll
            for (int mf = 0; mf < 4; mf++)
                #pragma unroll
                for (int nf = 0; nf < 4; nf++)
                    mma_f16(acc[mf][nf][0], acc[mf][nf][1],
                            acc[mf][nf][2], acc[mf][nf][3],
                            a[mf][0], a[mf][1], a[mf][2], a[mf][3],
                            bh[nf][0], bh[nf][1]);
        }
        __syncthreads();   // stage fully consumed before it is overwritten
    }

    // ---- epilogue ----
    #pragma unroll
    for (int mf = 0; mf < 4; mf++) {
        const int mrow = m0 + wm * 64 + mf * 16 + (lane >> 2);
        #pragma unroll
        for (int nf = 0; nf < 4; nf++) {
            const int ncol = n0 + wn * 32 + nf * 8 + (lane & 3) * 2;
            if (mrow < N_NODES) {
                float2* p = reinterpret_cast<float2*>(out + (size_t)mrow * N_OUT + ncol);
                *p = make_float2(acc[mf][nf][0], acc[mf][nf][1]);
            }
            if (mrow + 8 < N_NODES) {
                float2* p = reinterpret_cast<float2*>(out + (size_t)(mrow + 8) * N_OUT + ncol);
                *p = make_float2(acc[mf][nf][2], acc[mf][nf][3]);
            }
        }
    }
}

// ---------------------------------------------------------------------------
// Launch
// ---------------------------------------------------------------------------
extern "C" void kernel_launch(void* const* d_in, const int* in_sizes, int n_in,
                              void* d_out, int out_size)
{
    const float* x    = (const float*)d_in[0];
    const float* vals = (const float*)d_in[1];
    const float* W    = (const float*)d_in[2];
    const int*   row  = (const int*)d_in[3];
    const int*   col  = (const int*)d_in[4];
    float*       out  = (float*)d_out;

    int E = in_sizes[1];

    static bool s_init = false;
    if (!s_init) {
        cudaFuncSetAttribute(mma_gemm_kernel,
                             cudaFuncAttributeMaxDynamicSharedMemorySize, GEMM_SMEM);
        s_init = true;
    }

    zero_cnt_kernel<<<(N_NODES + 511) / 512, 512>>>();
    hist_kernel<<<(E + 511) / 512, 512>>>(row, E);
    scan_kernel<<<1, 1024>>>();
    fill_kernel<<<(E + 511) / 512, 512>>>(vals, row, col, E);
    gather_split_kernel<<<(N_NODES + 3) / 4, 512>>>(x);
    split_w_kernel<<<256, 256>>>(W);

    dim3 grid(N_OUT / GBN, M_PAD / GBM);   // (4, 157)
    mma_gemm_kernel<<<grid, 256, GEMM_SMEM>>>(out);
}

// round 15
// speedup vs baseline: 1.6729x; 1.3107x over previous
#include <cuda_runtime.h>
#include <cuda_fp16.h>
#include <cstdint>

#define N_NODES 20000
#define N_EDGES 160000
#define N_IN    512
#define N_OUT   512
#define M_PAD   20096            // 157 * 128

// Static device scratch (no runtime allocation; zero-initialized at load)
__device__ __half         g_Ahi[(size_t)M_PAD * N_IN];   // 20.6 MB (padding rows stay 0)
__device__ __half         g_Whi[(size_t)N_OUT * N_IN];   // 0.5 MB
__device__ int            g_cnt[N_NODES];                // histogram, then fill cursor
__device__ int            g_ofs[N_NODES + 1];            // CSR row offsets
__device__ int            g_csr_col[N_EDGES];
__device__ float          g_csr_val[N_EDGES];

// ---------------------------------------------------------------------------
// Helpers
// ---------------------------------------------------------------------------
__device__ __forceinline__ uint32_t smem_u32(const void* p) {
    uint32_t a;
    asm("{ .reg .u64 t; cvta.to.shared.u64 t, %1; cvt.u32.u64 %0, t; }"
        : "=r"(a) : "l"(p));
    return a;
}

__device__ __forceinline__ void cp_async16(uint32_t smem_addr, const void* gptr) {
    asm volatile("cp.async.cg.shared.global [%0], [%1], 16;"
                 :: "r"(smem_addr), "l"(gptr) : "memory");
}

__device__ __forceinline__ void ldsm_x4(uint32_t& r0, uint32_t& r1,
                                        uint32_t& r2, uint32_t& r3, uint32_t addr) {
    asm volatile("ldmatrix.sync.aligned.m8n8.x4.shared.b16 {%0,%1,%2,%3}, [%4];"
                 : "=r"(r0), "=r"(r1), "=r"(r2), "=r"(r3) : "r"(addr));
}

__device__ __forceinline__ void mma_f16(float& c0, float& c1, float& c2, float& c3,
                                        uint32_t a0, uint32_t a1, uint32_t a2, uint32_t a3,
                                        uint32_t b0, uint32_t b1) {
    asm volatile(
        "mma.sync.aligned.m16n8k16.row.col.f32.f16.f16.f32 "
        "{%0,%1,%2,%3}, {%4,%5,%6,%7}, {%8,%9}, {%0,%1,%2,%3};"
        : "+f"(c0), "+f"(c1), "+f"(c2), "+f"(c3)
        : "r"(a0), "r"(a1), "r"(a2), "r"(a3), "r"(b0), "r"(b1));
}

// SW128 swizzle for 128-byte rows
__device__ __forceinline__ uint32_t sw128(uint32_t off) {
    return off ^ ((off >> 3) & 0x70);
}

// ---------------------------------------------------------------------------
// CSR build: zero counts -> histogram -> scan -> fill
// ---------------------------------------------------------------------------
__global__ void zero_cnt_kernel() {
    int i = blockIdx.x * blockDim.x + threadIdx.x;
    if (i < N_NODES) g_cnt[i] = 0;
}

__global__ void hist_kernel(const int* __restrict__ row, int E) {
    int e = blockIdx.x * blockDim.x + threadIdx.x;
    if (e < E) atomicAdd(&g_cnt[row[e]], 1);
}

// Single-block exclusive scan of g_cnt -> g_ofs; re-init g_cnt as fill cursor.
__global__ __launch_bounds__(1024) void scan_kernel() {
    __shared__ int s[1024];
    const int t = threadIdx.x;
    const int PER = 20;                        // 1024*20 = 20480 >= N_NODES
    const int beg = t * PER;
    const int end = min(beg + PER, N_NODES);

    int part = 0;
    for (int i = beg; i < end; i++) part += g_cnt[i];
    s[t] = part;
    __syncthreads();
    for (int off = 1; off < 1024; off <<= 1) {
        int v = (t >= off) ? s[t - off] : 0;
        __syncthreads();
        s[t] += v;
        __syncthreads();
    }
    int base = s[t] - part;                    // exclusive prefix
    for (int i = beg; i < end; i++) {
        int c = g_cnt[i];
        g_ofs[i] = base;
        g_cnt[i] = base;                       // cursor for fill
        base += c;
    }
    if (t == 1023) g_ofs[N_NODES] = base;      // == E (tail parts are 0)
}

__global__ void fill_kernel(const float* __restrict__ vals,
                            const int* __restrict__ row,
                            const int* __restrict__ col, int E) {
    int e = blockIdx.x * blockDim.x + threadIdx.x;
    if (e < E) {
        int p = atomicAdd(&g_cnt[row[e]], 1);
        g_csr_col[p] = col[e];
        g_csr_val[p] = vals[e];
    }
}

// ---------------------------------------------------------------------------
// Gather + fp16 convert: one node per 128 threads (4 nodes / 512-thread block).
// ---------------------------------------------------------------------------
__global__ __launch_bounds__(512) void gather_split_kernel(const float* __restrict__ x)
{
    const int node = blockIdx.x * 4 + (threadIdx.x >> 7);
    if (node >= N_NODES) return;
    const int f4 = threadIdx.x & 127;

    const int beg = g_ofs[node];
    const int end = g_ofs[node + 1];

    float4 acc = make_float4(0.f, 0.f, 0.f, 0.f);
    for (int p = beg; p < end; p++) {
        const int   c = g_csr_col[p];          // warp-uniform (broadcast)
        const float v = g_csr_val[p];
        float4 xv = reinterpret_cast<const float4*>(x + (size_t)c * N_IN)[f4];
        acc.x += v * xv.x; acc.y += v * xv.y;
        acc.z += v * xv.z; acc.w += v * xv.w;
    }

    __half2 H0 = __halves2half2(__float2half_rn(acc.x), __float2half_rn(acc.y));
    __half2 H1 = __halves2half2(__float2half_rn(acc.z), __float2half_rn(acc.w));
    uint2* hp = reinterpret_cast<uint2*>(g_Ahi + (size_t)node * N_IN) + f4;
    *hp = make_uint2(*reinterpret_cast<uint32_t*>(&H0),
                     *reinterpret_cast<uint32_t*>(&H1));
}

// ---------------------------------------------------------------------------
// W convert to fp16
// ---------------------------------------------------------------------------
__global__ void split_w_kernel(const float* __restrict__ W) {
    const int n4 = (N_OUT * N_IN) / 4;
    uint32_t* hi = reinterpret_cast<uint32_t*>(g_Whi);
    const float4* src = reinterpret_cast<const float4*>(W);
    for (int i = blockIdx.x * blockDim.x + threadIdx.x; i < n4;
         i += gridDim.x * blockDim.x) {
        float4 f = src[i];
        __half2 H0 = __halves2half2(__float2half_rn(f.x), __float2half_rn(f.y));
        __half2 H1 = __halves2half2(__float2half_rn(f.z), __float2half_rn(f.w));
        hi[i * 2]     = *reinterpret_cast<uint32_t*>(&H0);
        hi[i * 2 + 1] = *reinterpret_cast<uint32_t*>(&H1);
    }
}

// ---------------------------------------------------------------------------
// GEMM: out = agg @ W^T via mma.sync fp16, single chain, fp32 accum.
// Block tile 128x128, K=64 stages (2 tiles x 16 KB = 32 KB/stage),
// double-buffered (64 KB) -> 2 CTAs/SM. SW128 rows (R10-proven addressing).
// ---------------------------------------------------------------------------
#define GBM 128
#define GBN 128
#define NSTEP (N_IN / 64)      // 8 K-steps of 64

#define T_AHI 0
#define T_BHI 16384
#define STAGE_SZ 32768
#define GEMM_SMEM (2 * STAGE_SZ)   // 64 KB

__global__ __launch_bounds__(256, 2) void mma_gemm_kernel(float* __restrict__ out)
{
    extern __shared__ __align__(1024) char smem[];
    const uint32_t sbase = smem_u32(smem);
    const int tid = threadIdx.x;
    const int wid = tid >> 5;
    const int lane = tid & 31;
    const int wm = wid >> 2;            // 0..1 : rows wm*64
    const int wn = wid & 3;             // 0..3 : cols wn*32
    const int m0 = blockIdx.y * GBM;
    const int n0 = blockIdx.x * GBN;

    const int r = tid >> 1;             // 0..127 (tile row this thread loads)
    const int h = tid & 1;              // 0..1   (which 64B half of the 128B row)
    const char* srcA = (const char*)(g_Ahi + (size_t)(m0 + r) * N_IN);
    const char* srcB = (const char*)(g_Whi + (size_t)(n0 + r) * N_IN);

    // Load one K64 step (2 tiles x 128 rows x 128B) into a stage; commit group.
    auto load_step = [&](int step, uint32_t stg) {
        const int cbyte = step * 128;                // 64 fp16 = 128B per row
        #pragma unroll
        for (int jj = 0; jj < 4; jj++) {
            const int j = h * 4 + jj;                // 16B chunk 0..7
            const uint32_t dst = sw128((uint32_t)(r * 128 + j * 16));
            const int so = cbyte + j * 16;
            cp_async16(sbase + stg + T_AHI + dst, srcA + so);
            cp_async16(sbase + stg + T_BHI + dst, srcB + so);
        }
        asm volatile("cp.async.commit_group;" ::: "memory");
    };

    float acc[4][4][4];
    #pragma unroll
    for (int i = 0; i < 4; i++)
        #pragma unroll
        for (int j = 0; j < 4; j++)
            #pragma unroll
            for (int k = 0; k < 4; k++) acc[i][j][k] = 0.f;

    load_step(0, 0);   // prologue

    for (int s = 0; s < NSTEP; s++) {
        const uint32_t stg = (uint32_t)(s & 1) * STAGE_SZ;

        if (s + 1 < NSTEP) {
            load_step(s + 1, (uint32_t)((s + 1) & 1) * STAGE_SZ);
            asm volatile("cp.async.wait_group 1;" ::: "memory");  // step s landed
        } else {
            asm volatile("cp.async.wait_group 0;" ::: "memory");
        }
        __syncthreads();

        #pragma unroll
        for (int ks = 0; ks < 4; ks++) {     // four K16 sub-steps per stage
            uint32_t a[4][4], bh[4][2];

            // A fragments
            #pragma unroll
            for (int mf = 0; mf < 4; mf++) {
                uint32_t off = (uint32_t)((wm * 64 + mf * 16 +
                               ((lane >> 3) & 1) * 8 + (lane & 7)) * 128
                               + ks * 32 + (lane >> 4) * 16);
                ldsm_x4(a[mf][0], a[mf][1], a[mf][2], a[mf][3],
                        sbase + stg + T_AHI + sw128(off));
            }
            // B fragments
            #pragma unroll
            for (int nf2 = 0; nf2 < 2; nf2++) {
                uint32_t off = (uint32_t)((wn * 32 + nf2 * 16 +
                               ((lane >> 4) & 1) * 8 + (lane & 7)) * 128
                               + ks * 32 + ((lane >> 3) & 1) * 16);
                ldsm_x4(bh[nf2 * 2][0], bh[nf2 * 2][1],
                        bh[nf2 * 2 + 1][0], bh[nf2 * 2 + 1][1],
                        sbase + stg + T_BHI + sw128(off));
            }
            #pragma unroll
            for (int mf = 0; mf < 4; mf++)
                #pragma unroll
                for (int nf = 0; nf < 4; nf++)
                    mma_f16(acc[mf][nf][0], acc[mf][nf][1],
                            acc[mf][nf][2], acc[mf][nf][3],
                            a[mf][0], a[mf][1], a[mf][2], a[mf][3],
                            bh[nf][0], bh[nf][1]);
        }
        __syncthreads();   // stage fully consumed before it is overwritten
    }

    // ---- epilogue ----
    #pragma unroll
    for (int mf = 0; mf < 4; mf++) {
        const int mrow = m0 + wm * 64 + mf * 16 + (lane >> 2);
        #pragma unroll
        for (int nf = 0; nf < 4; nf++) {
            const int ncol = n0 + wn * 32 + nf * 8 + (lane & 3) * 2;
            if (mrow < N_NODES) {
                float2* p = reinterpret_cast<float2*>(out + (size_t)mrow * N_OUT + ncol);
                *p = make_float2(acc[mf][nf][0], acc[mf][nf][1]);
            }
            if (mrow + 8 < N_NODES) {
                float2* p = reinterpret_cast<float2*>(out + (size_t)(mrow + 8) * N_OUT + ncol);
                *p = make_float2(acc[mf][nf][2], acc[mf][nf][3]);
            }
        }
    }
}

// ---------------------------------------------------------------------------
// Launch
// ---------------------------------------------------------------------------
extern "C" void kernel_launch(void* const* d_in, const int* in_sizes, int n_in,
                              void* d_out, int out_size)
{
    const float* x    = (const float*)d_in[0];
    const float* vals = (const float*)d_in[1];
    const float* W    = (const float*)d_in[2];
    const int*   row  = (const int*)d_in[3];
    const int*   col  = (const int*)d_in[4];
    float*       out  = (float*)d_out;

    int E = in_sizes[1];

    static bool s_init = false;
    if (!s_init) {
        cudaFuncSetAttribute(mma_gemm_kernel,
                             cudaFuncAttributeMaxDynamicSharedMemorySize, GEMM_SMEM);
        s_init = true;
    }

    zero_cnt_kernel<<<(N_NODES + 511) / 512, 512>>>();
    hist_kernel<<<(E + 511) / 512, 512>>>(row, E);
    scan_kernel<<<1, 1024>>>();
    fill_kernel<<<(E + 511) / 512, 512>>>(vals, row, col, E);
    gather_split_kernel<<<(N_NODES + 3) / 4, 512>>>(x);
    split_w_kernel<<<256, 256>>>(W);

    dim3 grid(N_OUT / GBN, M_PAD / GBM);   // (4, 157)
    mma_gemm_kernel<<<grid, 256, GEMM_SMEM>>>(out);
}